// round 11
// baseline (speedup 1.0000x reference)
#include <cuda_runtime.h>
#include <cuda_bf16.h>

// out shape (1, 8, 4096, 4096) fp32, 512 MiB of stores.
// c in 0..3:  out[c][i][j] = table[seq[i]*4 + c]      (row splat, constant over j)
// c in 4..7:  out[c][i][j] = table[seq[j]*4 + (c-4)]  (identical 16KB pattern every i)
//
// Persistent grid: 148 SMs x 8 resident blocks = 1184 blocks, ONE wave.
// Each block owns a contiguous chunk of 28 rows (~448KB extent) and streams
// float4 .cs stores continuously -- no wave-transition / block-ramp bubbles.

#define L 4096
#define NB 4
#define NUM_SMS 148
#define BLOCKS_PER_SM 8
#define GRID (NUM_SMS * BLOCKS_PER_SM)          // 1184
#define TOTAL_ROWS (2 * NB * L)                 // 32768
#define CHUNK ((TOTAL_ROWS + GRID - 1) / GRID)  // 28

__global__ __launch_bounds__(256, BLOCKS_PER_SM)
void seq_embed_kernel(const int* __restrict__ seq,
                      const float* __restrict__ table,
                      float* __restrict__ out)
{
    const int t = threadIdx.x;

    __shared__ float tbl[NB * NB];
    if (t < NB * NB) tbl[t] = table[t];
    __syncthreads();

    const int row_begin = blockIdx.x * CHUNK;
    const int row_end   = min(row_begin + CHUNK, TOTAL_ROWS);

    const int4* seq4 = reinterpret_cast<const int4*>(seq);

    for (int row = row_begin; row < row_end; ++row) {
        const int c = row >> 12;        // row / 4096
        const int i = row & (L - 1);    // row % 4096

        float4* row4 = reinterpret_cast<float4*>(out) + (size_t)row * (L / 4);

        if (c < NB) {
            // splat row: constant value across j
            const float v = tbl[seq[i] * NB + c];
            const float4 f4 = make_float4(v, v, v, v);
#pragma unroll
            for (int k = 0; k < 4; ++k)
                __stcs(row4 + t + 256 * k, f4);
        } else {
            const int cc = c - NB;
#pragma unroll
            for (int k = 0; k < 4; ++k) {
                const int4 s = __ldg(seq4 + t + 256 * k);  // 16KB, L1/L2-resident
                const float4 f4 = make_float4(tbl[s.x * NB + cc],
                                              tbl[s.y * NB + cc],
                                              tbl[s.z * NB + cc],
                                              tbl[s.w * NB + cc]);
                __stcs(row4 + t + 256 * k, f4);
            }
        }
    }
}

extern "C" void kernel_launch(void* const* d_in, const int* in_sizes, int n_in,
                              void* d_out, int out_size)
{
    const int*   seq   = (const int*)d_in[0];    // seq_ids (int32)
    const float* table = (const float*)d_in[1];  // base_table (4x4)
    float*       out   = (float*)d_out;          // (1, 8, 4096, 4096) fp32

    seq_embed_kernel<<<GRID, 256>>>(seq, table, out);
}

// round 15
// speedup vs baseline: 1.1908x; 1.1908x over previous
#include <cuda_runtime.h>
#include <cuda_bf16.h>

// out shape (1, 8, 4096, 4096) fp32, 512 MiB of stores.
// c in 0..3:  out[c][i][j] = table[seq[i]*4 + c]      (row splat, constant over j)
// c in 4..7:  out[c][i][j] = table[seq[j]*4 + (c-4)]  (identical 16KB pattern every i)
//
// One 16KB row per block, 128 threads, 8 independent float4 .cs stores per
// thread (deep store batch keeps DRAM write queue full across block churn);
// HW block scheduler provides load balancing (persistent chunks regressed).
//
// (Resubmission of R11 kernel -- previous bench died on container infra,
//  theory still untested.)

#define L 4096
#define NB 4
#define THREADS 128
#define VPT 8   // float4 stores per thread: 128*8*4 = 4096 floats = one row

__global__ __launch_bounds__(THREADS, 16)
void seq_embed_kernel(const int* __restrict__ seq,
                      const float* __restrict__ table,
                      float* __restrict__ out)
{
    const int i = blockIdx.x;   // 0..4095
    const int c = blockIdx.y;   // 0..7
    const int t = threadIdx.x;

    __shared__ float tbl[NB * NB];
    if (t < NB * NB) tbl[t] = table[t];
    __syncthreads();

    float4* row4 = reinterpret_cast<float4*>(
        out + (((size_t)c * L) + (size_t)i) * (size_t)L);

    if (c < NB) {
        // splat row: constant value across j
        const float v = tbl[seq[i] * NB + c];
        const float4 f4 = make_float4(v, v, v, v);
#pragma unroll
        for (int k = 0; k < VPT; ++k)
            __stcs(row4 + t + THREADS * k, f4);
    } else {
        const int cc = c - NB;
        const int4* seq4 = reinterpret_cast<const int4*>(seq);
        // front-batch all 8 gathers (16KB seq is L1-resident), then burst stores
        int4 s[VPT];
#pragma unroll
        for (int k = 0; k < VPT; ++k)
            s[k] = __ldg(seq4 + t + THREADS * k);
#pragma unroll
        for (int k = 0; k < VPT; ++k) {
            const float4 f4 = make_float4(tbl[s[k].x * NB + cc],
                                          tbl[s[k].y * NB + cc],
                                          tbl[s[k].z * NB + cc],
                                          tbl[s[k].w * NB + cc]);
            __stcs(row4 + t + THREADS * k, f4);
        }
    }
}

extern "C" void kernel_launch(void* const* d_in, const int* in_sizes, int n_in,
                              void* d_out, int out_size)
{
    const int*   seq   = (const int*)d_in[0];    // seq_ids (int32)
    const float* table = (const float*)d_in[1];  // base_table (4x4)
    float*       out   = (float*)d_out;          // (1, 8, 4096, 4096) fp32

    dim3 grid(L, 2 * NB);
    seq_embed_kernel<<<grid, THREADS>>>(seq, table, out);
}